// round 16
// baseline (speedup 1.0000x reference)
#include <cuda_runtime.h>
#include <cstdint>

// Problem constants
#define BB    8
#define C     128
#define W     256
#define H     256
#define NPIX  (W*H)          // 65536 pixels per image
#define NBLK  512            // one wave (4/SM x 148 = 592 slots)
#define NB7   128            // b7 half-tile blocks (512 px each)
#define NTILE 448            // b0..6 full tiles in the dynamic queue
#define NCHK  512            // phase-2 chunks (ch x 4 segs)

// Output buffer layout (concatenated f32, raw reshapes):
#define OFF_CENTERS 0
#define OFF_LABELS  256
#define OFF_ONEHOT  (OFF_LABELS + BB*NPIX)
#define OFF_DIST    (OFF_ONEHOT + BB*2*NPIX)
#define OFF_LABELT  (OFF_DIST   + BB*2*NPIX)

// Scratch (__device__ globals; overwrite-slot semantics, counters self-reset).
// g_mask: batch-7 labels as bits; word j covers f4 indices [32j, 32j+32).
__device__ uint4 g_mask[512];
// g_part[(k*128+ch)*4 + seg]
__device__ float g_part[256 * 4];
__device__ int   g_ready_seg[4] = {0,0,0,0};  // 32 producers per segment
__device__ int   g_work   = 0;   // b0..6 tile queue head
__device__ int   g_work2  = 0;   // phase-2 chunk queue head
__device__ int   g_arrive = 0;   // terminal arrival counter

__device__ __forceinline__ float msel(unsigned m, int lane, float f) {
    return ((m >> lane) & 1u) ? f : 0.0f;
}

// ---------------------------------------------------------------------------
// Streaming b0..6 tile (proven roofline geometry, unchanged).
// ---------------------------------------------------------------------------
__device__ __forceinline__ void main_tile_stream(const float* __restrict__ F,
                                                 const float* __restrict__ sc,
                                                 float* __restrict__ out,
                                                 int b, int p4) {
    int n0 = p4 << 2;
    const float4* Fb = reinterpret_cast<const float4*>(F + (size_t)b * C * NPIX);

    float4 a0 = make_float4(0.f,0.f,0.f,0.f);
    float4 a1 = make_float4(0.f,0.f,0.f,0.f);
    #pragma unroll 8
    for (int ch = 0; ch < C; ch++) {
        float4 f = __ldcs(&Fb[ch * (NPIX/4) + p4]);
        float c0 = sc[ch], c1 = sc[C + ch];
        a0.x += f.x*c0; a0.y += f.y*c0; a0.z += f.z*c0; a0.w += f.w*c0;
        a1.x += f.x*c1; a1.y += f.y*c1; a1.z += f.z*c1; a1.w += f.w*c1;
    }

    float d0x = 0.5f - 0.5f*a0.x, d1x = 0.5f - 0.5f*a1.x;
    float d0y = 0.5f - 0.5f*a0.y, d1y = 0.5f - 0.5f*a1.y;
    float d0z = 0.5f - 0.5f*a0.z, d1z = 0.5f - 0.5f*a1.z;
    float d0w = 0.5f - 0.5f*a0.w, d1w = 0.5f - 0.5f*a1.w;

    int lx = d1x < d0x, ly = d1y < d0y, lz = d1z < d0z, lw = d1w < d0w;
    float4 lab = make_float4((float)lx, (float)ly, (float)lz, (float)lw);

    __stcs(reinterpret_cast<float4*>(out + OFF_LABELS + (size_t)b*NPIX + n0), lab);
    __stcs(reinterpret_cast<float4*>(out + OFF_LABELT + (size_t)b*NPIX + n0), lab);

    float4* outO = reinterpret_cast<float4*>(out + OFF_ONEHOT + (size_t)b*2*NPIX + 2*n0);
    __stcs(outO + 0, make_float4(1.f - lab.x, lab.x, 1.f - lab.y, lab.y));
    __stcs(outO + 1, make_float4(1.f - lab.z, lab.z, 1.f - lab.w, lab.w));

    float4* outD = reinterpret_cast<float4*>(out + OFF_DIST + (size_t)b*2*NPIX + 2*n0);
    __stcs(outD + 0, make_float4(d0x, d1x, d0y, d1y));
    __stcs(outD + 1, make_float4(d0z, d1z, d0w, d1w));
}

// ---------------------------------------------------------------------------
// Single kernel, 512 blocks x 256 threads, one wave.
// Blocks 0..127 : b7 half-tile (512 px, 2-sub channel split) -> masks
//                 published at ~t/2 -> join tile queue -> chunk queue.
// Blocks 128..511: tile queue -> chunk queue.
// Phase-2 chunks overlap the DRAM stream (early-free blocks eat them).
// Last-arriving block: popcount + centers epilogue + counter reset.
// ---------------------------------------------------------------------------
__global__ void __launch_bounds__(256, 4)
k_all(const float* __restrict__ F,
      const float* __restrict__ Cinit,
      float* __restrict__ out) {
    __shared__ float  sc[2*C];
    __shared__ float4 slab[128];    // b7 half-tile labels per f4 pixel
    __shared__ float  wa[8], w1[8];
    __shared__ int    wc[8];
    __shared__ int    s_done, s_cnt, s_t;

    int t    = threadIdx.x;
    int lane = t & 31;
    int warp = t >> 5;
    int blk  = blockIdx.x;

    sc[t] = Cinit[t];
    __syncthreads();

    if (blk < NB7) {
        // ============ b7 half-tile: 128 f4 pixels, 2 subs/pixel ============
        const float4* F7 = reinterpret_cast<const float4*>(
            F + (size_t)(BB-1) * C * NPIX);
        int p  = t >> 1;                 // local f4 pixel 0..127
        int s  = t & 1;                  // channel half
        int p4 = blk * 128 + p;          // global f4 pixel

        float a0x=0.f,a0y=0.f,a0z=0.f,a0w=0.f;
        float a1x=0.f,a1y=0.f,a1z=0.f,a1w=0.f;
        #pragma unroll 8
        for (int k = 0; k < 64; k++) {
            int ch = s*64 + k;
            float4 f = F7[(size_t)ch * (NPIX/4) + p4];   // default: L2-retain
            float c0 = sc[ch], c1 = sc[C + ch];
            a0x += f.x*c0; a0y += f.y*c0; a0z += f.z*c0; a0w += f.w*c0;
            a1x += f.x*c1; a1y += f.y*c1; a1z += f.z*c1; a1w += f.w*c1;
        }
        a0x += __shfl_xor_sync(0xffffffffu, a0x, 1);
        a0y += __shfl_xor_sync(0xffffffffu, a0y, 1);
        a0z += __shfl_xor_sync(0xffffffffu, a0z, 1);
        a0w += __shfl_xor_sync(0xffffffffu, a0w, 1);
        a1x += __shfl_xor_sync(0xffffffffu, a1x, 1);
        a1y += __shfl_xor_sync(0xffffffffu, a1y, 1);
        a1z += __shfl_xor_sync(0xffffffffu, a1z, 1);
        a1w += __shfl_xor_sync(0xffffffffu, a1w, 1);

        float d0x = 0.5f - 0.5f*a0x, d1x = 0.5f - 0.5f*a1x;
        float d0y = 0.5f - 0.5f*a0y, d1y = 0.5f - 0.5f*a1y;
        float d0z = 0.5f - 0.5f*a0z, d1z = 0.5f - 0.5f*a1z;
        float d0w = 0.5f - 0.5f*a0w, d1w = 0.5f - 0.5f*a1w;
        float4 lab = make_float4((float)(d1x<d0x), (float)(d1y<d0y),
                                 (float)(d1z<d0z), (float)(d1w<d0w));

        float4* L4 = reinterpret_cast<float4*>(out + OFF_LABELS + (size_t)(BB-1)*NPIX);
        float4* T4 = reinterpret_cast<float4*>(out + OFF_LABELT + (size_t)(BB-1)*NPIX);
        float4* O4 = reinterpret_cast<float4*>(out + OFF_ONEHOT + (size_t)(BB-1)*2*NPIX);
        float4* D4 = reinterpret_cast<float4*>(out + OFF_DIST   + (size_t)(BB-1)*2*NPIX);
        if (s == 0) {
            slab[p] = lab;
            __stcs(&L4[p4], lab);
            __stcs(&O4[2*p4],   make_float4(1.f-lab.x, lab.x, 1.f-lab.y, lab.y));
            __stcs(&D4[2*p4],   make_float4(d0x, d1x, d0y, d1y));
        } else {
            __stcs(&T4[p4], lab);
            __stcs(&O4[2*p4+1], make_float4(1.f-lab.z, lab.z, 1.f-lab.w, lab.w));
            __stcs(&D4[2*p4+1], make_float4(d0z, d1z, d0w, d1w));
        }
        __syncthreads();                 // slab complete

        // build + publish 4 mask words (warps 0..3)
        if (warp < 4) {
            float4 l = slab[warp*32 + lane];
            unsigned bx = __ballot_sync(0xffffffffu, l.x != 0.f);
            unsigned by = __ballot_sync(0xffffffffu, l.y != 0.f);
            unsigned bz = __ballot_sync(0xffffffffu, l.z != 0.f);
            unsigned bw = __ballot_sync(0xffffffffu, l.w != 0.f);
            if (lane == 0) g_mask[blk*4 + warp] = make_uint4(bx, by, bz, bw);
        }
        __syncthreads();
        if (t == 0) {
            __threadfence();                          // publish masks
            atomicAdd(&g_ready_seg[blk >> 5], 1);     // 32 producers/segment
        }
    }

    // ================= dynamic queue: 448 b0..6 tiles =================
    for (;;) {
        __syncthreads();
        if (t == 0) s_t = atomicAdd(&g_work, 1);
        __syncthreads();
        int tt = s_t;
        if (tt >= NTILE) break;
        int b    = tt >> 6;
        int slot = tt & 63;
        main_tile_stream(F, sc, out, b, slot * 256 + t);
    }

    // ================= dynamic queue: 512 phase-2 chunks =================
    for (;;) {
        __syncthreads();
        if (t == 0) s_t = atomicAdd(&g_work2, 1);
        __syncthreads();
        int cc = s_t;
        if (cc >= NCHK) break;
        int ch  = cc & 127;
        int seg = cc >> 7;                 // 0..3, 4096 f4 per segment

        if (t == 0) {                      // masks ready ~t/2; short/no spin
            volatile int* r = &g_ready_seg[seg];
            while (*r < 32) __nanosleep(128);
        }
        __syncthreads();
        __threadfence();                   // acquire masks

        const float4* Fp = reinterpret_cast<const float4*>(
            F + ((size_t)(BB-1) * C + ch) * NPIX) + seg * 4096;
        const uint4* Mp = g_mask + seg * 128;

        float sa0 = 0.f, sa1 = 0.f, s10 = 0.f, s11 = 0.f;
        #pragma unroll
        for (int i = 0; i < 16; i += 2) {
            int j0 = i*256 + t, j1 = (i+1)*256 + t;
            float4 f0 = Fp[j0];
            float4 f1 = Fp[j1];
            uint4  m0 = Mp[j0 >> 5];
            uint4  m1 = Mp[j1 >> 5];
            sa0 += (f0.x + f0.y) + (f0.z + f0.w);
            sa1 += (f1.x + f1.y) + (f1.z + f1.w);
            s10 += (msel(m0.x, lane, f0.x) + msel(m0.y, lane, f0.y))
                 + (msel(m0.z, lane, f0.z) + msel(m0.w, lane, f0.w));
            s11 += (msel(m1.x, lane, f1.x) + msel(m1.y, lane, f1.y))
                 + (msel(m1.z, lane, f1.z) + msel(m1.w, lane, f1.w));
        }
        float sa = sa0 + sa1;
        float s1 = s10 + s11;
        #pragma unroll
        for (int o = 16; o > 0; o >>= 1) {
            sa += __shfl_down_sync(0xffffffffu, sa, o);
            s1 += __shfl_down_sync(0xffffffffu, s1, o);
        }
        if (lane == 0) { wa[warp] = sa; w1[warp] = s1; }
        __syncthreads();
        if (t == 0) {
            float va = 0.f, v1 = 0.f;
            #pragma unroll
            for (int i = 0; i < 8; i++) { va += wa[i]; v1 += w1[i]; }
            g_part[(ch)     * 4 + seg] = va - v1;   // label 0 sum
            g_part[(C + ch) * 4 + seg] = v1;        // label 1 sum
        }
    }

    // ================ terminal arrival; last block: epilogue ================
    if (t == 0) {
        __threadfence();
        int old = atomicAdd(&g_arrive, 1);
        s_done = (old == NBLK - 1);
    }
    __syncthreads();
    if (!s_done) return;
    __threadfence();

    // label-1 count via mask popcount (512 uint4 / 256 threads = 2 each)
    {
        uint4 m0 = g_mask[2*t], m1 = g_mask[2*t + 1];
        int c = __popc(m0.x) + __popc(m0.y) + __popc(m0.z) + __popc(m0.w)
              + __popc(m1.x) + __popc(m1.y) + __popc(m1.z) + __popc(m1.w);
        #pragma unroll
        for (int o = 16; o > 0; o >>= 1)
            c += __shfl_down_sync(0xffffffffu, c, o);
        if (lane == 0) wc[warp] = c;
        __syncthreads();
        if (t == 0) {
            int v = 0;
            #pragma unroll
            for (int i = 0; i < 8; i++) v += wc[i];
            s_cnt = v;
        }
        __syncthreads();
    }

    float sum = 0.f;
    #pragma unroll
    for (int i = 0; i < 4; i++) sum += __ldcg(&g_part[t*4 + i]);

    int k = t >> 7;
    float num = (k ? (float)s_cnt : (float)(NPIX - s_cnt)) + 1.0f;
    float mean = sum / num;
    float ci = sc[t];
    out[OFF_CENTERS + t] = ci + 0.001f * (mean - ci);

    if (t == 0) {                          // reset for next graph replay
        g_arrive = 0; g_work = 0; g_work2 = 0;
        g_ready_seg[0] = 0; g_ready_seg[1] = 0;
        g_ready_seg[2] = 0; g_ready_seg[3] = 0;
    }
}

// ---------------------------------------------------------------------------
extern "C" void kernel_launch(void* const* d_in, const int* in_sizes, int n_in,
                              void* d_out, int out_size) {
    const float* F     = (const float*)d_in[0];   // FeatureT [8,128,256,256]
    const float* Cinit = (const float*)d_in[1];   // centerInit [2,128]
    float* out = (float*)d_out;
    (void)in_sizes; (void)n_in; (void)out_size;

    k_all<<<NBLK, 256>>>(F, Cinit, out);
}